// round 8
// baseline (speedup 1.0000x reference)
#include <cuda_runtime.h>
#include <cuda_bf16.h>
#include <stdint.h>
#include <math.h>

#define Bt 4
#define Tt 2048
#define Dd 1024
#define Ee 8
#define Ff 2752
#define TOPK 2
#define Ntok (Bt*Tt)        // 8192 tokens
#define NR   (Ntok*TOPK)    // 16384 routed rows

typedef signed char s8;

// ======================= device scratch (static, no allocs) =======================
__device__ s8    g_x8h[(size_t)Ntok * Dd];
__device__ s8    g_x8l[(size_t)Ntok * Dd];
__device__ s8    g_wg8h[(size_t)Ee * Ff * Dd];   // [e][n(F)][k(D)]
__device__ s8    g_wg8l[(size_t)Ee * Ff * Dd];
__device__ s8    g_wu8h[(size_t)Ee * Ff * Dd];
__device__ s8    g_wu8l[(size_t)Ee * Ff * Dd];
__device__ s8    g_wd8h[(size_t)Ee * Dd * Ff];   // [e][n(D)][k(F)]
__device__ s8    g_wd8l[(size_t)Ee * Dd * Ff];
__device__ s8    g_h8h[(size_t)NR * Ff];
__device__ s8    g_h8l[(size_t)NR * Ff];
__device__ float g_h32[(size_t)NR * Ff];         // fp32 intermediate h
__device__ float g_y[(size_t)NR * Dd];
__device__ float g_sx[Ntok];
__device__ float g_swg[Ee * Ff];
__device__ float g_swu[Ee * Ff];
__device__ float g_swd[Ee * Dd];
__device__ float g_sh[NR];
__device__ int   g_row_token[NR];
__device__ int   g_pos[Ntok * TOPK];
__device__ int   g_tok_eid[Ntok * TOPK];
__device__ float g_tok_w[Ntok * TOPK];
__device__ int   g_counts[Ee];
__device__ int   g_offs[Ee + 1];
__device__ int   g_cursor[Ee];
__device__ int   g_tile_off[Ee + 1];
__device__ float g_load[Ee];

// ======================= helpers =======================
__device__ __forceinline__ uint32_t smem_u32(const void* p) {
    uint32_t a;
    asm("{ .reg .u64 t; cvta.to.shared.u64 t, %1; cvt.u32.u64 %0, t; }" : "=r"(a) : "l"(p));
    return a;
}

#define CPASYNC(dst, src) \
    asm volatile("cp.async.cg.shared.global [%0], [%1], 16;" :: "r"(dst), "l"(src) : "memory")
#define CPCOMMIT() asm volatile("cp.async.commit_group;" ::: "memory")
#define CPWAIT1()  asm volatile("cp.async.wait_group 1;" ::: "memory")
#define CPWAIT0()  asm volatile("cp.async.wait_group 0;" ::: "memory")

#define LDMX4(r0, r1, r2, r3, a) \
    asm volatile("ldmatrix.sync.aligned.m8n8.x4.shared.b16 {%0,%1,%2,%3}, [%4];" \
        : "=r"(r0), "=r"(r1), "=r"(r2), "=r"(r3) : "r"(a))
#define LDMX2(r0, r1, a) \
    asm volatile("ldmatrix.sync.aligned.m8n8.x2.shared.b16 {%0,%1}, [%2];" \
        : "=r"(r0), "=r"(r1) : "r"(a))

#define MMA_S8(c, a, b) \
    asm volatile("mma.sync.aligned.m16n8k32.row.col.s32.s8.s8.s32 " \
        "{%0,%1,%2,%3}, {%4,%5,%6,%7}, {%8,%9}, {%0,%1,%2,%3};" \
        : "+r"((c)[0]), "+r"((c)[1]), "+r"((c)[2]), "+r"((c)[3]) \
        : "r"((a)[0]), "r"((a)[1]), "r"((a)[2]), "r"((a)[3]), "r"((b)[0]), "r"((b)[1]))

// 64B int8 payload rows padded to 80B: conflict-free for cp.async + ldmatrix phases
#define RSTR 80
#define A_T (128 * RSTR)                 // 10240 per hi/lo A tile
#define G1_BOFF (2 * A_T)                // 20480
#define G1_BMAT (32 * RSTR)              // 2560 per B matrix (32 n-rows)
#define G1_STAGE (2 * A_T + 4 * G1_BMAT) // 30720
#define G2_BMAT (64 * RSTR)              // 5120 per B matrix (64 n-rows)
#define G2_STAGE (2 * A_T + 2 * G2_BMAT) // 30720
#define STAGE 30720
#define SMEM_TOT (2 * STAGE + 1280)      // stages + tokS(512)+sxs(512)+sb(256)

__device__ __forceinline__ float q7(float x) {
    return fminf(fmaxf(rintf(x), -127.0f), 127.0f);
}

// ======================= pass 0: zero metadata =======================
__global__ void __launch_bounds__(32) zero_meta_kernel() {
    int t = threadIdx.x;
    if (t < Ee) { g_counts[t] = 0; g_load[t] = 0.0f; }
}

// ======================= quantize x (per-token row scale) =======================
__global__ void __launch_bounds__(256) quant_x_kernel(const float* __restrict__ x) {
    int warp = (blockIdx.x * 256 + threadIdx.x) >> 5;
    int lane = threadIdx.x & 31;
    if (warp >= Ntok) return;
    const float* xr = x + (size_t)warp * Dd;
    float v[32], mx = 0.0f;
#pragma unroll
    for (int j = 0; j < 32; j++) { v[j] = xr[lane + 32 * j]; mx = fmaxf(mx, fabsf(v[j])); }
#pragma unroll
    for (int o = 16; o; o >>= 1) mx = fmaxf(mx, __shfl_xor_sync(0xffffffffu, mx, o));
    mx = fmaxf(mx, 1e-30f);
    float sa = mx / 127.0f, inv = 127.0f / mx;
    if (lane == 0) g_sx[warp] = sa;
#pragma unroll
    for (int j = 0; j < 32; j++) {
        float hi = q7(v[j] * inv);
        float r = v[j] - hi * sa;
        float lo = q7(r * inv * 256.0f);
        g_x8h[(size_t)warp * Dd + lane + 32 * j] = (s8)hi;
        g_x8l[(size_t)warp * Dd + lane + 32 * j] = (s8)lo;
    }
}

// ======================= per-output-column weight max =======================
// src [e][K][N]; out scale[e][N] = colmax/127
__global__ void __launch_bounds__(256) wmax_kernel(const float* __restrict__ src,
                                                   float* __restrict__ sc, int K, int N) {
    int n = blockIdx.x * 256 + threadIdx.x;
    int e = blockIdx.y;
    if (n >= N) return;
    const float* p = src + (size_t)e * K * N + n;
    float mx = 0.0f;
    for (int k = 0; k < K; k++) mx = fmaxf(mx, fabsf(p[(size_t)k * N]));
    sc[e * N + n] = fmaxf(mx, 1e-30f) / 127.0f;
}

// ======================= transpose + int8 hi/lo quantize =======================
// src [z][K][N] -> dst [z][N][K] int8 hi/lo with per-n scale
__global__ void __launch_bounds__(256) tsplit_q_kernel(const float* __restrict__ src,
                                                       const float* __restrict__ sc,
                                                       s8* __restrict__ dhi,
                                                       s8* __restrict__ dlo,
                                                       int K, int N) {
    __shared__ float t[32][33];
    size_t base = (size_t)blockIdx.z * K * N;
    int n0 = blockIdx.x * 32, k0 = blockIdx.y * 32;
#pragma unroll
    for (int i = 0; i < 4; i++) {
        int k = k0 + threadIdx.y + i * 8;
        t[threadIdx.y + i * 8][threadIdx.x] = src[base + (size_t)k * N + n0 + threadIdx.x];
    }
    __syncthreads();
#pragma unroll
    for (int i = 0; i < 4; i++) {
        int n = n0 + threadIdx.y + i * 8;
        float sa = sc[blockIdx.z * N + n];
        float inv = 1.0f / sa;
        float v = t[threadIdx.x][threadIdx.y + i * 8];
        float hi = q7(v * inv);
        float r = v - hi * sa;
        float lo = q7(r * inv * 256.0f);
        size_t o = base + (size_t)n * K + k0 + threadIdx.x;
        dhi[o] = (s8)hi;
        dlo[o] = (s8)lo;
    }
}

// ======================= gating (exact fp32) =======================
__global__ void __launch_bounds__(128) gate_kernel(const float* __restrict__ x,
                                                   const float* __restrict__ gw) {
    int warp = (blockIdx.x * blockDim.x + threadIdx.x) >> 5;
    int lane = threadIdx.x & 31;
    if (warp >= Ntok) return;
    const float* xr = x + (size_t)warp * Dd;
    float xv[32];
#pragma unroll
    for (int j = 0; j < 32; j++) xv[j] = xr[j * 32 + lane];
    float p[Ee];
#pragma unroll
    for (int e = 0; e < Ee; e++) {
        float s = 0.0f;
#pragma unroll
        for (int j = 0; j < 32; j++) s += xv[j] * gw[(j * 32 + lane) * Ee + e];
#pragma unroll
        for (int o = 16; o; o >>= 1) s += __shfl_xor_sync(0xffffffffu, s, o);
        p[e] = s;
    }
    float mx = p[0];
#pragma unroll
    for (int e = 1; e < Ee; e++) mx = fmaxf(mx, p[e]);
    float den = 0.0f;
#pragma unroll
    for (int e = 0; e < Ee; e++) { p[e] = expf(p[e] - mx); den += p[e]; }
    float inv = 1.0f / den;
#pragma unroll
    for (int e = 0; e < Ee; e++) p[e] *= inv;
    int i1 = 0;
#pragma unroll
    for (int e = 1; e < Ee; e++) if (p[e] > p[i1]) i1 = e;
    int i2 = -1; float b2 = -1.0f;
#pragma unroll
    for (int e = 0; e < Ee; e++) {
        if (e == i1) continue;
        if (p[e] > b2) { b2 = p[e]; i2 = e; }
    }
    float s2 = p[i1] + p[i2] + 1e-8f;
    if (lane == 0) {
        g_tok_eid[warp * 2 + 0] = i1;
        g_tok_eid[warp * 2 + 1] = i2;
        g_tok_w[warp * 2 + 0] = p[i1] / s2;
        g_tok_w[warp * 2 + 1] = p[i2] / s2;
        atomicAdd(&g_counts[i1], 1);
        atomicAdd(&g_counts[i2], 1);
#pragma unroll
        for (int e = 0; e < Ee; e++) atomicAdd(&g_load[e], p[e]);
    }
}

// ======================= scan / build =======================
__global__ void __launch_bounds__(32) scan_kernel() {
    if (threadIdx.x != 0) return;
    int s = 0, ts = 0;
    for (int e = 0; e < Ee; e++) {
        g_offs[e] = s; g_cursor[e] = s; g_tile_off[e] = ts;
        ts += (g_counts[e] + 127) / 128;
        s += g_counts[e];
    }
    g_offs[Ee] = s; g_tile_off[Ee] = ts;
}

__global__ void __launch_bounds__(256) build_kernel() {
    int t = blockIdx.x * blockDim.x + threadIdx.x;
    if (t >= Ntok) return;
#pragma unroll
    for (int k = 0; k < TOPK; k++) {
        int e = g_tok_eid[t * 2 + k];
        int r = atomicAdd(&g_cursor[e], 1);
        g_row_token[r] = t;
        g_pos[t * 2 + k] = r;
    }
}

// ======================= gemm1: int8 3-term, M128 x N32(gate+up), BK=64 =======================
extern "C" __global__ void __launch_bounds__(256, 2)
gemm1_i8_kernel() {
    extern __shared__ __align__(16) char smem[];
    int tid = threadIdx.x, wid = tid >> 5, lane = tid & 31;
    int grp = lane >> 2, tig = lane & 3;
    int mw = wid & 3, nw = wid >> 2;

    int j = blockIdx.y;
    if (j >= g_tile_off[Ee]) return;
    int e = 0;
#pragma unroll
    for (int q = 0; q < Ee - 1; q++) if (j >= g_tile_off[q + 1]) e = q + 1;
    int mt0 = j - g_tile_off[e];
    int rowStart = g_offs[e] + mt0 * 128;
    int end = g_offs[e + 1];
    int n0 = blockIdx.x * 32;

    uint32_t sb = smem_u32(smem);
    int*   tokS = (int*)(smem + 2 * STAGE);
    float* sxs  = (float*)(smem + 2 * STAGE + 512);
    float* sbg  = (float*)(smem + 2 * STAGE + 1024);
    float* sbu  = (float*)(smem + 2 * STAGE + 1152);
    if (tid < 128) {
        int rr = rowStart + tid; if (rr > end - 1) rr = end - 1;
        int tk = g_row_token[rr];
        tokS[tid] = tk;
        sxs[tid] = g_sx[tk];
    }
    if (tid >= 128 && tid < 160) {
        sbg[tid - 128] = g_swg[e * Ff + n0 + tid - 128];
        sbu[tid - 128] = g_swu[e * Ff + n0 + tid - 128];
    }
    __syncthreads();

    const s8* wq[4];
    wq[0] = g_wg8h + ((size_t)e * Ff + n0) * Dd;
    wq[1] = g_wg8l + ((size_t)e * Ff + n0) * Dd;
    wq[2] = g_wu8h + ((size_t)e * Ff + n0) * Dd;
    wq[3] = g_wu8l + ((size_t)e * Ff + n0) * Dd;

    int cgm[2][2][4] = {}, cgx[2][2][4] = {}, cum[2][2][4] = {}, cux[2][2][4] = {};
    const int NIT = Dd / 64;  // 16

    uint32_t aoff = (uint32_t)((mw * 32 + (lane & 15)) * RSTR + (lane >> 4) * 16);
    uint32_t boff2 = (uint32_t)(((lane & 15) & 7) * RSTR + (((lane & 15) >> 3) & 1) * 16);

    auto issue = [&](int it) {
        uint32_t stu = sb + (it & 1) * STAGE;
        int k0 = it * 64;
#pragma unroll
        for (int q = 0; q < 6; q++) {
            int c = tid + q * 256;
            if (c < 1024) {                     // A hi/lo: 2 arr * 128 rows * 4 chunks
                int arr = c >> 9, idx = c & 511, row = idx >> 2, ck = idx & 3;
                const s8* src = (arr ? g_x8l : g_x8h) + (size_t)tokS[row] * Dd + k0 + ck * 16;
                CPASYNC(stu + arr * A_T + row * RSTR + ck * 16, src);
            } else {                            // B: 4 mats * 32 rows * 4 chunks
                int b = c - 1024, mat = b >> 7, idx = b & 127, row = idx >> 2, ck = idx & 3;
                const s8* src = wq[mat] + (size_t)row * Dd + k0 + ck * 16;
                CPASYNC(stu + G1_BOFF + mat * G1_BMAT + row * RSTR + ck * 16, src);
            }
        }
        CPCOMMIT();
    };

    issue(0);
    for (int it = 0; it < NIT; it++) {
        if (it + 1 < NIT) { issue(it + 1); CPWAIT1(); } else { CPWAIT0(); }
        __syncthreads();
        uint32_t stu = sb + (it & 1) * STAGE;
#pragma unroll
        for (int kb = 0; kb < 2; kb++) {
            uint32_t ah[2][4], al[2][4];
#pragma unroll
            for (int mt = 0; mt < 2; mt++) {
                uint32_t ab = stu + aoff + mt * (16 * RSTR) + kb * 32;
                LDMX4(ah[mt][0], ah[mt][1], ah[mt][2], ah[mt][3], ab);
                LDMX4(al[mt][0], al[mt][1], al[mt][2], al[mt][3], ab + A_T);
            }
#pragma unroll
            for (int g = 0; g < 2; g++) {
                uint32_t bb = stu + G1_BOFF + (nw * 16 + g * 8) * RSTR + kb * 32 + boff2;
                uint32_t bgh[2], bgl[2], buh[2], bul[2];
                LDMX2(bgh[0], bgh[1], bb);
                LDMX2(bgl[0], bgl[1], bb + G1_BMAT);
                LDMX2(buh[0], buh[1], bb + 2 * G1_BMAT);
                LDMX2(bul[0], bul[1], bb + 3 * G1_BMAT);
#pragma unroll
                for (int mt = 0; mt < 2; mt++) {
                    MMA_S8(cgm[mt][g], ah[mt], bgh);
                    MMA_S8(cgx[mt][g], al[mt], bgh);
                    MMA_S8(cgx[mt][g], ah[mt], bgl);
                    MMA_S8(cum[mt][g], ah[mt], buh);
                    MMA_S8(cux[mt][g], al[mt], buh);
                    MMA_S8(cux[mt][g], ah[mt], bul);
                }
            }
        }
        __syncthreads();
    }

    // epilogue: dequant, SwiGLU, store fp32 h
    const float inv256 = 1.0f / 256.0f;
#pragma unroll
    for (int mt = 0; mt < 2; mt++) {
#pragma unroll
        for (int half = 0; half < 2; half++) {
            int rl = mw * 32 + mt * 16 + grp + half * 8;
            int row = rowStart + rl;
            if (row >= end) continue;
            float sa = sxs[rl];
#pragma unroll
            for (int g = 0; g < 2; g++) {
                int cl = nw * 16 + g * 8 + tig * 2;
                float g0 = sa * sbg[cl]     * ((float)cgm[mt][g][half * 2]     + (float)cgx[mt][g][half * 2]     * inv256);
                float g1 = sa * sbg[cl + 1] * ((float)cgm[mt][g][half * 2 + 1] + (float)cgx[mt][g][half * 2 + 1] * inv256);
                float u0 = sa * sbu[cl]     * ((float)cum[mt][g][half * 2]     + (float)cux[mt][g][half * 2]     * inv256);
                float u1 = sa * sbu[cl + 1] * ((float)cum[mt][g][half * 2 + 1] + (float)cux[mt][g][half * 2 + 1] * inv256);
                float z0 = g0 / (1.0f + expf(-g0)) * u0;
                float z1 = g1 / (1.0f + expf(-g1)) * u1;
                *(float2*)(g_h32 + (size_t)row * Ff + n0 + cl) = make_float2(z0, z1);
            }
        }
    }
}

// ======================= quantize h (per-routed-row scale) =======================
__global__ void __launch_bounds__(256) quant_h_kernel() {
    __shared__ float red[256];
    int row = blockIdx.x, tid = threadIdx.x;
    const float* hp = g_h32 + (size_t)row * Ff;
    float mx = 0.0f;
    for (int i = tid; i < Ff; i += 256) mx = fmaxf(mx, fabsf(hp[i]));
    red[tid] = mx; __syncthreads();
    for (int s = 128; s; s >>= 1) {
        if (tid < s) red[tid] = fmaxf(red[tid], red[tid + s]);
        __syncthreads();
    }
    float m = fmaxf(red[0], 1e-30f);
    float sa = m / 127.0f, inv = 127.0f / m;
    if (tid == 0) g_sh[row] = sa;
    for (int i = tid; i < Ff; i += 256) {
        float v = hp[i];
        float hi = q7(v * inv);
        float r = v - hi * sa;
        float lo = q7(r * inv * 256.0f);
        g_h8h[(size_t)row * Ff + i] = (s8)hi;
        g_h8l[(size_t)row * Ff + i] = (s8)lo;
    }
}

// ======================= gemm2: int8 3-term, M128 x N64, BK=64 =======================
extern "C" __global__ void __launch_bounds__(256, 2)
gemm2_i8_kernel() {
    extern __shared__ __align__(16) char smem[];
    int tid = threadIdx.x, wid = tid >> 5, lane = tid & 31;
    int grp = lane >> 2, tig = lane & 3;
    int mw = wid & 3, nw = wid >> 2;

    int j = blockIdx.y;
    if (j >= g_tile_off[Ee]) return;
    int e = 0;
#pragma unroll
    for (int q = 0; q < Ee - 1; q++) if (j >= g_tile_off[q + 1]) e = q + 1;
    int mt0 = j - g_tile_off[e];
    int rowStart = g_offs[e] + mt0 * 128;
    int end = g_offs[e + 1];
    int n0 = blockIdx.x * 64;

    uint32_t sb = smem_u32(smem);
    float* shs  = (float*)(smem + 2 * STAGE);
    float* swds = (float*)(smem + 2 * STAGE + 512);
    if (tid < 128) {
        int rr = rowStart + tid; if (rr > end - 1) rr = end - 1;
        shs[tid] = g_sh[rr];
    }
    if (tid >= 128 && tid < 192) swds[tid - 128] = g_swd[e * Dd + n0 + tid - 128];
    __syncthreads();

    const s8* wdh = g_wd8h + ((size_t)e * Dd + n0) * Ff;
    const s8* wdl = g_wd8l + ((size_t)e * Dd + n0) * Ff;

    int cm[2][4][4] = {}, cx[2][4][4] = {};
    const int NIT = Ff / 64;  // 43

    uint32_t aoff = (uint32_t)((mw * 32 + (lane & 15)) * RSTR + (lane >> 4) * 16);
    uint32_t boff2 = (uint32_t)(((lane & 15) & 7) * RSTR + (((lane & 15) >> 3) & 1) * 16);

    auto issue = [&](int it) {
        uint32_t stu = sb + (it & 1) * STAGE;
        int k0 = it * 64;
#pragma unroll
        for (int q = 0; q < 6; q++) {
            int c = tid + q * 256;
            if (c < 1024) {                     // A (h) hi/lo
                int arr = c >> 9, idx = c & 511, row = idx >> 2, ck = idx & 3;
                int rr = rowStart + row; if (rr > end - 1) rr = end - 1;
                const s8* src = (arr ? g_h8l : g_h8h) + (size_t)rr * Ff + k0 + ck * 16;
                CPASYNC(stu + arr * A_T + row * RSTR + ck * 16, src);
            } else {                            // B (wd) hi/lo: 2 arr * 64 rows * 4 chunks
                int b = c - 1024, arr = b >> 8, idx = b & 255, row = idx >> 2, ck = idx & 3;
                const s8* src = (arr ? wdl : wdh) + (size_t)row * Ff + k0 + ck * 16;
                CPASYNC(stu + G1_BOFF + arr * G2_BMAT + row * RSTR + ck * 16, src);
            }
        }
        CPCOMMIT();
    };

    issue(0);
    for (int it = 0; it < NIT; it++) {
        if (it + 1 < NIT) { issue(it + 1); CPWAIT1(); } else { CPWAIT0(); }
        __syncthreads();
        uint32_t stu = sb + (it & 1) * STAGE;
#pragma unroll
        for (int kb = 0; kb < 2; kb++) {
            uint32_t ah[2][4], al[2][4];
#pragma unroll
            for (int mt = 0; mt < 2; mt++) {
                uint32_t ab = stu + aoff + mt * (16 * RSTR) + kb * 32;
                LDMX4(ah[mt][0], ah[mt][1], ah[mt][2], ah[mt][3], ab);
                LDMX4(al[mt][0], al[mt][1], al[mt][2], al[mt][3], ab + A_T);
            }
#pragma unroll
            for (int g = 0; g < 4; g++) {
                uint32_t bb = stu + G1_BOFF + (nw * 32 + g * 8) * RSTR + kb * 32 + boff2;
                uint32_t bh[2], bl[2];
                LDMX2(bh[0], bh[1], bb);
                LDMX2(bl[0], bl[1], bb + G2_BMAT);
#pragma unroll
                for (int mt = 0; mt < 2; mt++) {
                    MMA_S8(cm[mt][g], ah[mt], bh);
                    MMA_S8(cx[mt][g], al[mt], bh);
                    MMA_S8(cx[mt][g], ah[mt], bl);
                }
            }
        }
        __syncthreads();
    }

    const float inv256 = 1.0f / 256.0f;
#pragma unroll
    for (int mt = 0; mt < 2; mt++) {
#pragma unroll
        for (int half = 0; half < 2; half++) {
            int rl = mw * 32 + mt * 16 + grp + half * 8;
            int row = rowStart + rl;
            if (row >= end) continue;
            float sa = shs[rl];
#pragma unroll
            for (int g = 0; g < 4; g++) {
                int cl = nw * 32 + g * 8 + tig * 2;
                float y0 = sa * swds[cl]     * ((float)cm[mt][g][half * 2]     + (float)cx[mt][g][half * 2]     * inv256);
                float y1 = sa * swds[cl + 1] * ((float)cm[mt][g][half * 2 + 1] + (float)cx[mt][g][half * 2 + 1] * inv256);
                *(float2*)(g_y + (size_t)row * Dd + n0 + cl) = make_float2(y0, y1);
            }
        }
    }
}

// ======================= combine =======================
__global__ void __launch_bounds__(256) combine_kernel(float* __restrict__ out) {
    const int nq = Ntok * (Dd / 4);
    for (int idx = blockIdx.x * blockDim.x + threadIdx.x; idx < nq;
         idx += gridDim.x * blockDim.x) {
        int t = idx / (Dd / 4);
        int dq = idx - t * (Dd / 4);
        int p0 = g_pos[t * 2 + 0], p1 = g_pos[t * 2 + 1];
        float w0 = g_tok_w[t * 2 + 0], w1 = g_tok_w[t * 2 + 1];
        float4 a = *(const float4*)(g_y + (size_t)p0 * Dd + dq * 4);
        float4 b = *(const float4*)(g_y + (size_t)p1 * Dd + dq * 4);
        float4 o;
        o.x = w0 * a.x + w1 * b.x;
        o.y = w0 * a.y + w1 * b.y;
        o.z = w0 * a.z + w1 * b.z;
        o.w = w0 * a.w + w1 * b.w;
        *(float4*)(out + (size_t)t * Dd + dq * 4) = o;
    }
}

// ======================= aux loss =======================
__global__ void __launch_bounds__(32) aux_kernel(float* __restrict__ out, int out_size) {
    if (threadIdx.x != 0 || blockIdx.x != 0) return;
    float s = 0.0f;
    for (int e = 0; e < Ee; e++) {
        float load = g_load[e] / (float)Ntok;
        float frac = (float)g_counts[e] / (float)(Ntok * TOPK);
        s += frac * load;
    }
    float aux = 0.01f * (float)Ee * s;
    for (int i = Ntok * Dd; i < out_size; i++) out[i] = aux;
}

// ======================= launch =======================
extern "C" void kernel_launch(void* const* d_in, const int* in_sizes, int n_in,
                              void* d_out, int out_size) {
    const float* x      = (const float*)d_in[0];
    const float* gate_w = (const float*)d_in[1];
    const float* w_gate = (const float*)d_in[2];
    const float* w_up   = (const float*)d_in[3];
    const float* w_down = (const float*)d_in[4];
    float* out = (float*)d_out;

    cudaFuncSetAttribute(gemm1_i8_kernel, cudaFuncAttributeMaxDynamicSharedMemorySize, SMEM_TOT);
    cudaFuncSetAttribute(gemm2_i8_kernel, cudaFuncAttributeMaxDynamicSharedMemorySize, SMEM_TOT);

    float *swg_p, *swu_p, *swd_p;
    s8 *wg8h_p, *wg8l_p, *wu8h_p, *wu8l_p, *wd8h_p, *wd8l_p;
    cudaGetSymbolAddress((void**)&swg_p, g_swg);
    cudaGetSymbolAddress((void**)&swu_p, g_swu);
    cudaGetSymbolAddress((void**)&swd_p, g_swd);
    cudaGetSymbolAddress((void**)&wg8h_p, g_wg8h);
    cudaGetSymbolAddress((void**)&wg8l_p, g_wg8l);
    cudaGetSymbolAddress((void**)&wu8h_p, g_wu8h);
    cudaGetSymbolAddress((void**)&wu8l_p, g_wu8l);
    cudaGetSymbolAddress((void**)&wd8h_p, g_wd8h);
    cudaGetSymbolAddress((void**)&wd8l_p, g_wd8l);

    zero_meta_kernel<<<1, 32>>>();
    quant_x_kernel<<<Ntok / 8, 256>>>(x);

    wmax_kernel<<<dim3((Ff + 255) / 256, Ee), 256>>>(w_gate, swg_p, Dd, Ff);
    wmax_kernel<<<dim3((Ff + 255) / 256, Ee), 256>>>(w_up,   swu_p, Dd, Ff);
    wmax_kernel<<<dim3((Dd + 255) / 256, Ee), 256>>>(w_down, swd_p, Ff, Dd);

    dim3 tb(32, 8);
    tsplit_q_kernel<<<dim3(Ff / 32, Dd / 32, Ee), tb>>>(w_gate, swg_p, wg8h_p, wg8l_p, Dd, Ff);
    tsplit_q_kernel<<<dim3(Ff / 32, Dd / 32, Ee), tb>>>(w_up,   swu_p, wu8h_p, wu8l_p, Dd, Ff);
    tsplit_q_kernel<<<dim3(Dd / 32, Ff / 32, Ee), tb>>>(w_down, swd_p, wd8h_p, wd8l_p, Ff, Dd);

    gate_kernel<<<Ntok / 4, 128>>>(x, gate_w);
    scan_kernel<<<1, 32>>>();
    build_kernel<<<(Ntok + 255) / 256, 256>>>();

    gemm1_i8_kernel<<<dim3(Ff / 32, 136), 256, SMEM_TOT>>>();
    quant_h_kernel<<<NR, 256>>>();
    gemm2_i8_kernel<<<dim3(Dd / 64, 136), 256, SMEM_TOT>>>();

    combine_kernel<<<1184, 256>>>(out);
    aux_kernel<<<1, 32>>>(out, out_size);
}

// round 11
// speedup vs baseline: 2.7774x; 2.7774x over previous
#include <cuda_runtime.h>
#include <cuda_bf16.h>
#include <stdint.h>
#include <math.h>

#define Bt 4
#define Tt 2048
#define Dd 1024
#define Ee 8
#define Ff 2752
#define TOPK 2
#define Ntok (Bt*Tt)        // 8192 tokens
#define NR   (Ntok*TOPK)    // 16384 routed rows

// ======================= device scratch (static, no allocs) =======================
__device__ __nv_bfloat16 g_x_hi[(size_t)Ntok * Dd];
__device__ __nv_bfloat16 g_x_lo[(size_t)Ntok * Dd];
__device__ __nv_bfloat16 g_wg_hi[(size_t)Ee * Ff * Dd];   // [e][n(F)][k(D)]
__device__ __nv_bfloat16 g_wg_lo[(size_t)Ee * Ff * Dd];
__device__ __nv_bfloat16 g_wu_hi[(size_t)Ee * Ff * Dd];
__device__ __nv_bfloat16 g_wu_lo[(size_t)Ee * Ff * Dd];
__device__ __nv_bfloat16 g_wd_hi[(size_t)Ee * Dd * Ff];   // [e][n(D)][k(F)]
__device__ __nv_bfloat16 g_wd_lo[(size_t)Ee * Dd * Ff];
__device__ __nv_bfloat16 g_h_hi[(size_t)NR * Ff];         // [r][f]
__device__ __nv_bfloat16 g_h_lo[(size_t)NR * Ff];
__device__ float g_y[(size_t)NR * Dd];
__device__ int   g_row_token[NR];
__device__ int   g_pos[Ntok * TOPK];
__device__ int   g_tok_eid[Ntok * TOPK];
__device__ float g_tok_w[Ntok * TOPK];
__device__ int   g_counts[Ee];
__device__ int   g_offs[Ee + 1];
__device__ int   g_cursor[Ee];
__device__ int   g_tile_off[Ee + 1];
__device__ float g_load[Ee];

// ======================= helpers =======================
__device__ __forceinline__ uint32_t smem_u32(const void* p) {
    uint32_t a;
    asm("{ .reg .u64 t; cvta.to.shared.u64 t, %1; cvt.u32.u64 %0, t; }" : "=r"(a) : "l"(p));
    return a;
}

#define CPASYNC(dst, src) \
    asm volatile("cp.async.cg.shared.global [%0], [%1], 16;" :: "r"(dst), "l"(src) : "memory")
#define CPCOMMIT() asm volatile("cp.async.commit_group;" ::: "memory")
#define CPWAIT1()  asm volatile("cp.async.wait_group 1;" ::: "memory")
#define CPWAIT0()  asm volatile("cp.async.wait_group 0;" ::: "memory")

#define LDMX4(r0, r1, r2, r3, a) \
    asm volatile("ldmatrix.sync.aligned.m8n8.x4.shared.b16 {%0,%1,%2,%3}, [%4];" \
        : "=r"(r0), "=r"(r1), "=r"(r2), "=r"(r3) : "r"(a))

#define MMA_BF16(c, a, b) \
    asm volatile("mma.sync.aligned.m16n8k16.row.col.f32.bf16.bf16.f32 " \
        "{%0,%1,%2,%3}, {%4,%5,%6,%7}, {%8,%9}, {%0,%1,%2,%3};" \
        : "+f"((c)[0]), "+f"((c)[1]), "+f"((c)[2]), "+f"((c)[3]) \
        : "r"((a)[0]), "r"((a)[1]), "r"((a)[2]), "r"((a)[3]), "r"((b)[0]), "r"((b)[1]))

// padded row stride: 32 halves + 8 pad = 40 halves = 80 bytes (16B-aligned; r*80 mod 128
// is an 8-cycle => conflict-free for both cp.async stores and ldmatrix 8-row phases)
#define RSTR 80
#define A_TILE_B (128 * RSTR)        // 10240
#define B_TILE_B (64 * RSTR)         // 5120
#define G1_STAGE (2 * A_TILE_B + 4 * B_TILE_B)      // 40960
#define G2_STAGE (2 * A_TILE_B + 2 * (128 * RSTR))  // 40960
#define SMEM_TOT (2 * 40960 + 512)

// ======================= pass 0: zero metadata =======================
__global__ void __launch_bounds__(32) zero_meta_kernel() {
    int t = threadIdx.x;
    if (t < Ee) { g_counts[t] = 0; g_load[t] = 0.0f; }
}

// ======================= gating + x split (fused; exact fp32 routing) =======================
__global__ void __launch_bounds__(128) gate_kernel(const float* __restrict__ x,
                                                   const float* __restrict__ gw) {
    int warp = (blockIdx.x * blockDim.x + threadIdx.x) >> 5;
    int lane = threadIdx.x & 31;
    if (warp >= Ntok) return;
    const float* xr = x + (size_t)warp * Dd;
    float xv[32];
#pragma unroll
    for (int j = 0; j < 32; j++) xv[j] = xr[j * 32 + lane];

    // write bf16 hi/lo split of x (fused with gating; coalesced across lanes)
#pragma unroll
    for (int j = 0; j < 32; j++) {
        __nv_bfloat16 hi = __float2bfloat16(xv[j]);
        g_x_hi[(size_t)warp * Dd + j * 32 + lane] = hi;
        g_x_lo[(size_t)warp * Dd + j * 32 + lane] =
            __float2bfloat16(xv[j] - __bfloat162float(hi));
    }

    float p[Ee];
#pragma unroll
    for (int e = 0; e < Ee; e++) {
        float s = 0.0f;
#pragma unroll
        for (int j = 0; j < 32; j++) s += xv[j] * gw[(j * 32 + lane) * Ee + e];
#pragma unroll
        for (int o = 16; o; o >>= 1) s += __shfl_xor_sync(0xffffffffu, s, o);
        p[e] = s;
    }
    float mx = p[0];
#pragma unroll
    for (int e = 1; e < Ee; e++) mx = fmaxf(mx, p[e]);
    float den = 0.0f;
#pragma unroll
    for (int e = 0; e < Ee; e++) { p[e] = expf(p[e] - mx); den += p[e]; }
    float inv = 1.0f / den;
#pragma unroll
    for (int e = 0; e < Ee; e++) p[e] *= inv;
    int i1 = 0;
#pragma unroll
    for (int e = 1; e < Ee; e++) if (p[e] > p[i1]) i1 = e;
    int i2 = -1; float b2 = -1.0f;
#pragma unroll
    for (int e = 0; e < Ee; e++) {
        if (e == i1) continue;
        if (p[e] > b2) { b2 = p[e]; i2 = e; }
    }
    float s2 = p[i1] + p[i2] + 1e-8f;
    if (lane == 0) {
        g_tok_eid[warp * 2 + 0] = i1;
        g_tok_eid[warp * 2 + 1] = i2;
        g_tok_w[warp * 2 + 0] = p[i1] / s2;
        g_tok_w[warp * 2 + 1] = p[i2] / s2;
        atomicAdd(&g_counts[i1], 1);
        atomicAdd(&g_counts[i2], 1);
#pragma unroll
        for (int e = 0; e < Ee; e++) atomicAdd(&g_load[e], p[e]);
    }
}

// ======================= scan =======================
__global__ void __launch_bounds__(32) scan_kernel() {
    if (threadIdx.x != 0) return;
    int s = 0, ts = 0;
    for (int e = 0; e < Ee; e++) {
        g_offs[e] = s; g_cursor[e] = s; g_tile_off[e] = ts;
        ts += (g_counts[e] + 127) / 128;
        s += g_counts[e];
    }
    g_offs[Ee] = s; g_tile_off[Ee] = ts;
}

// ======================= routing build =======================
__global__ void __launch_bounds__(256) build_kernel() {
    int t = blockIdx.x * blockDim.x + threadIdx.x;
    if (t >= Ntok) return;
#pragma unroll
    for (int k = 0; k < TOPK; k++) {
        int e = g_tok_eid[t * 2 + k];
        int r = atomicAdd(&g_cursor[e], 1);
        g_row_token[r] = t;
        g_pos[t * 2 + k] = r;
    }
}

// ======================= prep: transpose + split wg & wu in one launch =======================
// z in [0,16): z<8 -> w_gate expert z ; z>=8 -> w_up expert z-8. src [e][D][F] -> dst [e][F][D]
__global__ void __launch_bounds__(256) tsplit_gu_kernel(const float* __restrict__ wg,
                                                        const float* __restrict__ wu) {
    __shared__ float t[32][33];
    int z = blockIdx.z;
    int e = z & 7;
    const float* src = (z < Ee ? wg : wu);
    __nv_bfloat16* dhi = (z < Ee ? g_wg_hi : g_wu_hi);
    __nv_bfloat16* dlo = (z < Ee ? g_wg_lo : g_wu_lo);
    size_t base = (size_t)e * Dd * Ff;
    int n0 = blockIdx.x * 32, k0 = blockIdx.y * 32;
#pragma unroll
    for (int i = 0; i < 4; i++) {
        int k = k0 + threadIdx.y + i * 8;
        t[threadIdx.y + i * 8][threadIdx.x] = src[base + (size_t)k * Ff + n0 + threadIdx.x];
    }
    __syncthreads();
#pragma unroll
    for (int i = 0; i < 4; i++) {
        int n = n0 + threadIdx.y + i * 8;
        float v = t[threadIdx.x][threadIdx.y + i * 8];
        __nv_bfloat16 hi = __float2bfloat16(v);
        size_t o = base + (size_t)n * Dd + k0 + threadIdx.x;
        dhi[o] = hi;
        dlo[o] = __float2bfloat16(v - __bfloat162float(hi));
    }
}

// wd: [e][F][D] -> [e][D][F]
__global__ void __launch_bounds__(256) tsplit_d_kernel(const float* __restrict__ wd) {
    __shared__ float t[32][33];
    int e = blockIdx.z;
    size_t base = (size_t)e * Ff * Dd;
    int n0 = blockIdx.x * 32, k0 = blockIdx.y * 32;
#pragma unroll
    for (int i = 0; i < 4; i++) {
        int k = k0 + threadIdx.y + i * 8;
        t[threadIdx.y + i * 8][threadIdx.x] = wd[base + (size_t)k * Dd + n0 + threadIdx.x];
    }
    __syncthreads();
#pragma unroll
    for (int i = 0; i < 4; i++) {
        int n = n0 + threadIdx.y + i * 8;
        float v = t[threadIdx.x][threadIdx.y + i * 8];
        __nv_bfloat16 hi = __float2bfloat16(v);
        size_t o = base + (size_t)n * Ff + k0 + threadIdx.x;
        g_wd_hi[o] = hi;
        g_wd_lo[o] = __float2bfloat16(v - __bfloat162float(hi));
    }
}

// ======================= gemm1: h = silu(Xg Wg) * (Xg Wu), mma.sync 3xbf16 =======================
// L2-friendly raster: groups of 8 m-tiles x all 43 n-tiles; m varies fastest within group.
extern "C" __global__ void __launch_bounds__(256, 2)
gemm1_mma_kernel() {
    extern __shared__ __align__(16) char smem[];
    int tid = threadIdx.x, wid = tid >> 5, lane = tid & 31;
    int grp = lane >> 2, tig = lane & 3;

    int bid = blockIdx.y * 43 + blockIdx.x;
    int group = bid / (43 * 8);
    int within = bid - group * (43 * 8);
    int j = group * 8 + (within & 7);         // m-tile index
    int nt = within >> 3;                     // n-tile index (0..42)

    if (j >= g_tile_off[Ee]) return;
    int e = 0;
#pragma unroll
    for (int q = 0; q < Ee - 1; q++) if (j >= g_tile_off[q + 1]) e = q + 1;
    int mt0 = j - g_tile_off[e];
    int rowStart = g_offs[e] + mt0 * 128;
    int end = g_offs[e + 1];
    int n0 = nt * 64;

    uint32_t sb = smem_u32(smem);
    int* tokS = (int*)(smem + 2 * G1_STAGE);
    if (tid < 128) {
        int rr = rowStart + tid; if (rr > end - 1) rr = end - 1;
        tokS[tid] = g_row_token[rr];
    }
    __syncthreads();

    const __nv_bfloat16* wb[4];
    wb[0] = g_wg_hi + ((size_t)e * Ff + n0) * Dd;
    wb[1] = g_wg_lo + ((size_t)e * Ff + n0) * Dd;
    wb[2] = g_wu_hi + ((size_t)e * Ff + n0) * Dd;
    wb[3] = g_wu_lo + ((size_t)e * Ff + n0) * Dd;

    float cg[2][4][4] = {}, cu[2][4][4] = {};
    const int NIT = Dd / 32;   // 32

    int mwbase = (wid & 3) * 32;
    int nwbase = (wid >> 2) * 32;
    uint32_t aoff = (uint32_t)((mwbase + (lane & 15)) * RSTR + (lane >> 4) * 16);
    uint32_t boff = (uint32_t)(2 * A_TILE_B +
                               (nwbase + ((lane >> 4) * 8) + (lane & 7)) * RSTR +
                               (((lane >> 3) & 1) * 16));

    auto issue = [&](int it) {
        uint32_t stu = sb + (it & 1) * G1_STAGE;
        int k0 = it * 32;
#pragma unroll
        for (int q = 0; q < 8; q++) {
            int c = tid + q * 256;
            if (c < 1024) {                     // A hi/lo: 2*128 rows * 4 chunks
                int arr = c >> 9, idx = c & 511, row = idx >> 2, cc = idx & 3;
                const __nv_bfloat16* src =
                    (arr ? g_x_lo : g_x_hi) + (size_t)tokS[row] * Dd + k0 + cc * 8;
                uint32_t dst = stu + arr * A_TILE_B + row * RSTR + cc * 16;
                CPASYNC(dst, src);
            } else {                            // B: 4 mats * 64 rows * 4 chunks
                int b = c - 1024, mat = b >> 8, idx = b & 255, row = idx >> 2, cc = idx & 3;
                const __nv_bfloat16* src = wb[mat] + (size_t)row * Dd + k0 + cc * 8;
                uint32_t dst = stu + 2 * A_TILE_B + mat * B_TILE_B + row * RSTR + cc * 16;
                CPASYNC(dst, src);
            }
        }
        CPCOMMIT();
    };

    issue(0);
    for (int it = 0; it < NIT; it++) {
        if (it + 1 < NIT) { issue(it + 1); CPWAIT1(); } else { CPWAIT0(); }
        __syncthreads();
        uint32_t stu = sb + (it & 1) * G1_STAGE;
#pragma unroll
        for (int ks = 0; ks < 2; ks++) {
            uint32_t kb = ks * 32;
            uint32_t ah[2][4], al[2][4];
#pragma unroll
            for (int mt = 0; mt < 2; mt++) {
                uint32_t ab = stu + aoff + mt * (16 * RSTR) + kb;
                LDMX4(ah[mt][0], ah[mt][1], ah[mt][2], ah[mt][3], ab);
                LDMX4(al[mt][0], al[mt][1], al[mt][2], al[mt][3], ab + A_TILE_B);
            }
#pragma unroll
            for (int ntp = 0; ntp < 2; ntp++) {
                uint32_t bb = stu + boff + ntp * (16 * RSTR) + kb;
                uint32_t gh[4], gl[4], uh[4], ul[4];
                LDMX4(gh[0], gh[1], gh[2], gh[3], bb);
                LDMX4(gl[0], gl[1], gl[2], gl[3], bb + B_TILE_B);
                LDMX4(uh[0], uh[1], uh[2], uh[3], bb + 2 * B_TILE_B);
                LDMX4(ul[0], ul[1], ul[2], ul[3], bb + 3 * B_TILE_B);
#pragma unroll
                for (int s2 = 0; s2 < 2; s2++) {
                    int ntc = ntp * 2 + s2;
                    uint32_t bgh[2] = {gh[2 * s2], gh[2 * s2 + 1]};
                    uint32_t bgl[2] = {gl[2 * s2], gl[2 * s2 + 1]};
                    uint32_t buh[2] = {uh[2 * s2], uh[2 * s2 + 1]};
                    uint32_t bul[2] = {ul[2 * s2], ul[2 * s2 + 1]};
#pragma unroll
                    for (int mt = 0; mt < 2; mt++) {
                        MMA_BF16(cg[mt][ntc], ah[mt], bgh);
                        MMA_BF16(cg[mt][ntc], al[mt], bgh);
                        MMA_BF16(cg[mt][ntc], ah[mt], bgl);
                        MMA_BF16(cu[mt][ntc], ah[mt], buh);
                        MMA_BF16(cu[mt][ntc], al[mt], buh);
                        MMA_BF16(cu[mt][ntc], ah[mt], bul);
                    }
                }
            }
        }
        __syncthreads();
    }

    // epilogue: SwiGLU, split to bf16 hi/lo, store
#pragma unroll
    for (int mt = 0; mt < 2; mt++) {
#pragma unroll
        for (int half = 0; half < 2; half++) {
            int row = rowStart + mwbase + mt * 16 + grp + half * 8;
            if (row >= end) continue;
#pragma unroll
            for (int ntc = 0; ntc < 4; ntc++) {
                int col = n0 + nwbase + ntc * 8 + tig * 2;
                float g0 = cg[mt][ntc][half * 2], g1 = cg[mt][ntc][half * 2 + 1];
                float u0 = cu[mt][ntc][half * 2], u1 = cu[mt][ntc][half * 2 + 1];
                float z0 = g0 / (1.0f + expf(-g0)) * u0;
                float z1 = g1 / (1.0f + expf(-g1)) * u1;
                __nv_bfloat16 h0 = __float2bfloat16(z0);
                __nv_bfloat16 h1 = __float2bfloat16(z1);
                __nv_bfloat16 l0 = __float2bfloat16(z0 - __bfloat162float(h0));
                __nv_bfloat16 l1 = __float2bfloat16(z1 - __bfloat162float(h1));
                __nv_bfloat162 hv; hv.x = h0; hv.y = h1;
                __nv_bfloat162 lv; lv.x = l0; lv.y = l1;
                *(__nv_bfloat162*)(g_h_hi + (size_t)row * Ff + col) = hv;
                *(__nv_bfloat162*)(g_h_lo + (size_t)row * Ff + col) = lv;
            }
        }
    }
}

// ======================= gemm2: y = h @ Wd, mma.sync 3xbf16 =======================
// raster: groups of 17 m-tiles x 8 n-tiles; m fastest within group.
extern "C" __global__ void __launch_bounds__(256, 2)
gemm2_mma_kernel() {
    extern __shared__ __align__(16) char smem[];
    int tid = threadIdx.x, wid = tid >> 5, lane = tid & 31;
    int grp = lane >> 2, tig = lane & 3;

    int bid = blockIdx.y * 8 + blockIdx.x;
    int group = bid / (17 * 8);
    int within = bid - group * (17 * 8);
    int j = group * 17 + (within % 17);
    int nt = within / 17;

    if (j >= g_tile_off[Ee]) return;
    int e = 0;
#pragma unroll
    for (int q = 0; q < Ee - 1; q++) if (j >= g_tile_off[q + 1]) e = q + 1;
    int mt0 = j - g_tile_off[e];
    int rowStart = g_offs[e] + mt0 * 128;
    int end = g_offs[e + 1];
    int n0 = nt * 128;

    uint32_t sb = smem_u32(smem);
    const __nv_bfloat16* wdh = g_wd_hi + ((size_t)e * Dd + n0) * Ff;
    const __nv_bfloat16* wdl = g_wd_lo + ((size_t)e * Dd + n0) * Ff;

    float cc_[2][8][4] = {};
    const int NIT = Ff / 32;    // 86
    const int BT = 128 * RSTR;  // 10240

    int mwbase = (wid & 3) * 32;
    int nwbase = (wid >> 2) * 64;
    uint32_t aoff = (uint32_t)((mwbase + (lane & 15)) * RSTR + (lane >> 4) * 16);
    uint32_t boff = (uint32_t)(2 * A_TILE_B +
                               (nwbase + ((lane >> 4) * 8) + (lane & 7)) * RSTR +
                               (((lane >> 3) & 1) * 16));

    auto issue = [&](int it) {
        uint32_t stu = sb + (it & 1) * G2_STAGE;
        int k0 = it * 32;
#pragma unroll
        for (int q = 0; q < 8; q++) {
            int c = tid + q * 256;
            if (c < 1024) {                     // A (h) hi/lo
                int arr = c >> 9, idx = c & 511, row = idx >> 2, ck = idx & 3;
                int rr = rowStart + row; if (rr > end - 1) rr = end - 1;
                const __nv_bfloat16* src =
                    (arr ? g_h_lo : g_h_hi) + (size_t)rr * Ff + k0 + ck * 8;
                uint32_t dst = stu + arr * A_TILE_B + row * RSTR + ck * 16;
                CPASYNC(dst, src);
            } else {                            // B (wd) hi/lo
                int b = c - 1024, arr = b >> 9, idx = b & 511, row = idx >> 2, ck = idx & 3;
                const __nv_bfloat16* src = (arr ? wdl : wdh) + (size_t)row * Ff + k0 + ck * 8;
                uint32_t dst = stu + 2 * A_TILE_B + arr * BT + row * RSTR + ck * 16;
                CPASYNC(dst, src);
            }
        }
        CPCOMMIT();
    };

    issue(0);
    for (int it = 0; it < NIT; it++) {
        if (it + 1 < NIT) { issue(it + 1); CPWAIT1(); } else { CPWAIT0(); }
        __syncthreads();
        uint32_t stu = sb + (it & 1) * G2_STAGE;
#pragma unroll
        for (int ks = 0; ks < 2; ks++) {
            uint32_t kb = ks * 32;
            uint32_t ah[2][4], al[2][4];
#pragma unroll
            for (int mt = 0; mt < 2; mt++) {
                uint32_t ab = stu + aoff + mt * (16 * RSTR) + kb;
                LDMX4(ah[mt][0], ah[mt][1], ah[mt][2], ah[mt][3], ab);
                LDMX4(al[mt][0], al[mt][1], al[mt][2], al[mt][3], ab + A_TILE_B);
            }
#pragma unroll
            for (int ntp = 0; ntp < 4; ntp++) {
                uint32_t bb = stu + boff + ntp * (16 * RSTR) + kb;
                uint32_t bh4[4], bl4[4];
                LDMX4(bh4[0], bh4[1], bh4[2], bh4[3], bb);
                LDMX4(bl4[0], bl4[1], bl4[2], bl4[3], bb + BT);
#pragma unroll
                for (int s2 = 0; s2 < 2; s2++) {
                    int ntc = ntp * 2 + s2;
                    uint32_t bh[2] = {bh4[2 * s2], bh4[2 * s2 + 1]};
                    uint32_t bl[2] = {bl4[2 * s2], bl4[2 * s2 + 1]};
#pragma unroll
                    for (int mt = 0; mt < 2; mt++) {
                        MMA_BF16(cc_[mt][ntc], ah[mt], bh);
                        MMA_BF16(cc_[mt][ntc], al[mt], bh);
                        MMA_BF16(cc_[mt][ntc], ah[mt], bl);
                    }
                }
            }
        }
        __syncthreads();
    }

#pragma unroll
    for (int mt = 0; mt < 2; mt++) {
#pragma unroll
        for (int half = 0; half < 2; half++) {
            int row = rowStart + mwbase + mt * 16 + grp + half * 8;
            if (row >= end) continue;
#pragma unroll
            for (int ntc = 0; ntc < 8; ntc++) {
                int col = n0 + nwbase + ntc * 8 + tig * 2;
                float2 v = make_float2(cc_[mt][ntc][half * 2], cc_[mt][ntc][half * 2 + 1]);
                *(float2*)(g_y + (size_t)row * Dd + col) = v;
            }
        }
    }
}

// ======================= combine =======================
__global__ void __launch_bounds__(256) combine_kernel(float* __restrict__ out) {
    const int nq = Ntok * (Dd / 4);
    for (int idx = blockIdx.x * blockDim.x + threadIdx.x; idx < nq;
         idx += gridDim.x * blockDim.x) {
        int t = idx / (Dd / 4);
        int dq = idx - t * (Dd / 4);
        int p0 = g_pos[t * 2 + 0], p1 = g_pos[t * 2 + 1];
        float w0 = g_tok_w[t * 2 + 0], w1 = g_tok_w[t * 2 + 1];
        float4 a = *(const float4*)(g_y + (size_t)p0 * Dd + dq * 4);
        float4 b = *(const float4*)(g_y + (size_t)p1 * Dd + dq * 4);
        float4 o;
        o.x = w0 * a.x + w1 * b.x;
        o.y = w0 * a.y + w1 * b.y;
        o.z = w0 * a.z + w1 * b.z;
        o.w = w0 * a.w + w1 * b.w;
        *(float4*)(out + (size_t)t * Dd + dq * 4) = o;
    }
}

// ======================= aux loss =======================
__global__ void __launch_bounds__(32) aux_kernel(float* __restrict__ out, int out_size) {
    if (threadIdx.x != 0 || blockIdx.x != 0) return;
    float s = 0.0f;
    for (int e = 0; e < Ee; e++) {
        float load = g_load[e] / (float)Ntok;
        float frac = (float)g_counts[e] / (float)(Ntok * TOPK);
        s += frac * load;
    }
    float aux = 0.01f * (float)Ee * s;
    for (int i = Ntok * Dd; i < out_size; i++) out[i] = aux;
}

// ======================= launch =======================
extern "C" void kernel_launch(void* const* d_in, const int* in_sizes, int n_in,
                              void* d_out, int out_size) {
    const float* x      = (const float*)d_in[0];
    const float* gate_w = (const float*)d_in[1];
    const float* w_gate = (const float*)d_in[2];
    const float* w_up   = (const float*)d_in[3];
    const float* w_down = (const float*)d_in[4];
    float* out = (float*)d_out;

    cudaFuncSetAttribute(gemm1_mma_kernel, cudaFuncAttributeMaxDynamicSharedMemorySize, SMEM_TOT);
    cudaFuncSetAttribute(gemm2_mma_kernel, cudaFuncAttributeMaxDynamicSharedMemorySize, SMEM_TOT);

    dim3 tb(32, 8);
    // launch order arranged so gemm1 is the 6th launch (ncu -s 5 -c 1 captures it)
    zero_meta_kernel<<<1, 32>>>();                               // 1
    gate_kernel<<<Ntok / 4, 128>>>(x, gate_w);                   // 2 (also splits x)
    scan_kernel<<<1, 32>>>();                                    // 3
    build_kernel<<<(Ntok + 255) / 256, 256>>>();                 // 4
    tsplit_gu_kernel<<<dim3(Ff / 32, Dd / 32, 16), tb>>>(w_gate, w_up);  // 5
    gemm1_mma_kernel<<<dim3(43, 136), 256, SMEM_TOT>>>();        // 6
    tsplit_d_kernel<<<dim3(Dd / 32, Ff / 32, Ee), tb>>>(w_down); // 7
    gemm2_mma_kernel<<<dim3(8, 136), 256, SMEM_TOT>>>();         // 8
    combine_kernel<<<1184, 256>>>(out);                          // 9
    aux_kernel<<<1, 32>>>(out, out_size);                        // 10
}